// round 14
// baseline (speedup 1.0000x reference)
#include <cuda_runtime.h>
#include <cuda_bf16.h>

#define NPTS 8192
#define NB 4
#define BDIM 128
#define ROWCH 512                       // rows per block
#define COLS_PER_BLK 256                // 4 warps x 64 cols
#define NROWCH (NPTS / ROWCH)           // 16
#define NCOLB (NPTS / COLS_PER_BLK)     // 32
#define NBLOCKS (NB * NROWCH * NCOLB)   // 2048
#define NCOMB 64

// Per-(dir,b,a) running min, key = ~bits(d), d>=0 -> min == atomicMax.
// Zero-init; idempotent across graph replays.
__device__ unsigned g_slot[2][NB][NPTS] = {};
__device__ float g_part[NCOMB][4];
__device__ int g_done;

#define PACK2(dst, lo, hi) \
    asm("mov.b64 %0, {%1, %2};" : "=l"(dst) : "r"(__float_as_uint(lo)), "r"(__float_as_uint(hi)))
#define UNPACK2(lo, hi, src) \
    { unsigned _ulo, _uhi; \
      asm("mov.b64 {%0, %1}, %2;" : "=r"(_ulo), "=r"(_uhi) : "l"(src)); \
      lo = __uint_as_float(_ulo); hi = __uint_as_float(_uhi); }
#define ADD2(d, a, b) \
    asm("add.rn.f32x2 %0, %1, %2;" : "=l"(d) : "l"(a), "l"(b))
#define FMA2(d, a, b, c) \
    asm("fma.rn.f32x2 %0, %1, %2, %3;" : "=l"(d) : "l"(a), "l"(b), "l"(c))
#define LDS_V2U64(r0, r1, addr) \
    asm volatile("ld.shared.v2.u64 {%0, %1}, [%2];" : "=l"(r0), "=l"(r1) : "r"(addr))

// Symmetric kernel: block = 512 rows (xyz1 chunk) x 256 cols (xyz2 chunk).
// Each distance computed ONCE; row-mins (dir0) via warp REDUX, col-mins (dir1)
// accumulate in each lane's registers for its fixed col-pair.
__global__ __launch_bounds__(BDIM, 7) void min_dist_kernel(
    const float* __restrict__ xyz1,
    const float* __restrict__ xyz2)
{
    // Row records (x,x,y,y | z,z,s1,s1) dup-packed: 512 * 32B = 16KB
    __shared__ __align__(16) unsigned long long sRow[ROWCH * 4];
    __shared__ int sRowp[4][ROWCH];     // per-warp row partial mins (bits), 8KB

    const int bx = blockIdx.x;
    if (bx == 0 && threadIdx.x == 0) g_done = 0;   // for combine (stream-ordered)

    const int colb  = bx & (NCOLB - 1);
    const int rowch = (bx >> 5) & (NROWCH - 1);
    const int b     = bx >> 9;

    const int tid  = threadIdx.x;
    const int wid  = tid >> 5;
    const int lane = tid & 31;

    // Prologue 1: dup-pack this block's 512 rows of xyz1 into smem.
    {
        const float2* R2 = (const float2*)(xyz1 + (size_t)(b * NPTS + rowch * ROWCH) * 3);
        #pragma unroll
        for (int i = 0; i < (ROWCH / 2) / BDIM; i++) {   // 2 row-pairs per thread
            const int j = i * BDIM + tid;                 // pair index 0..255
            float2 q0 = R2[3 * j + 0];   // x0 y0
            float2 q1 = R2[3 * j + 1];   // z0 x1
            float2 q2 = R2[3 * j + 2];   // y1 z1
            float s0 = q0.x * q0.x + q0.y * q0.y + q1.x * q1.x;
            float s1v = q1.y * q1.y + q2.x * q2.x + q2.y * q2.y;
            float4* dst = (float4*)sRow;
            dst[(2 * j + 0) * 2 + 0] = make_float4(q0.x, q0.x, q0.y, q0.y);
            dst[(2 * j + 0) * 2 + 1] = make_float4(q1.x, q1.x, s0, s0);
            dst[(2 * j + 1) * 2 + 0] = make_float4(q1.y, q1.y, q2.x, q2.x);
            dst[(2 * j + 1) * 2 + 1] = make_float4(q2.y, q2.y, s1v, s1v);
        }
    }

    // Prologue 2: this lane's fixed col-pair from xyz2, transformed into regs.
    const int colIdx = colb * COLS_PER_BLK + wid * 64 + lane * 2;
    unsigned long long X01, Y01, Z01, W01;
    {
        const float2* C2 = (const float2*)(xyz2 + (size_t)(b * NPTS + colIdx) * 3);
        float2 q0 = C2[0];   // x0 y0
        float2 q1 = C2[1];   // z0 x1
        float2 q2 = C2[2];   // y1 z1
        PACK2(X01, -2.0f * q0.x, -2.0f * q1.y);
        PACK2(Y01, -2.0f * q0.y, -2.0f * q2.x);
        PACK2(Z01, -2.0f * q1.x, -2.0f * q2.y);
        PACK2(W01, q0.x * q0.x + q0.y * q0.y + q1.x * q1.x,
                   q1.y * q1.y + q2.x * q2.x + q2.y * q2.y);
    }

    float cmin0 = 3.402823e38f;
    float cmin1 = 3.402823e38f;

    const unsigned sbase = (unsigned)__cvta_generic_to_shared(sRow);
    __syncthreads();

    // Mainloop: sweep 512 rows; each iter computes 2 dists/lane (64/warp) ONCE,
    // feeding both the row-min (warp REDUX) and the lane's col-min registers.
    #pragma unroll 8
    for (int r = 0; r < ROWCH; r++) {
        unsigned long long xx, yy, zz, ss, Ws, d;
        LDS_V2U64(xx, yy, sbase + r * 32);
        LDS_V2U64(zz, ss, sbase + r * 32 + 16);
        ADD2(Ws, W01, ss);                 // ||c||^2 + ||a||^2 (true distance)
        FMA2(d, X01, xx, Ws);
        FMA2(d, Y01, yy, d);
        FMA2(d, Z01, zz, d);
        float d0, d1;
        UNPACK2(d0, d1, d);
        cmin0 = fminf(cmin0, d0);
        cmin1 = fminf(cmin1, d1);
        float rp = fminf(d0, d1);
        // min.s32 on float bits == float min up to sign-bit patterns; any
        // negative-bits winner is a ~0 distance and is clamped in the tail.
        int k = __reduce_min_sync(0xffffffffu, __float_as_int(rp));
        if (lane == 0) sRowp[wid][r] = k;
    }
    __syncthreads();

    // Tail: publish row mins (dir0) and col mins (dir1) via atomicMax(~bits).
    #pragma unroll
    for (int i = 0; i < ROWCH / BDIM; i++) {      // 4 rows per thread
        const int r = i * BDIM + tid;
        int m = min(min(sRowp[0][r], sRowp[1][r]),
                    min(sRowp[2][r], sRowp[3][r]));
        float dr = fmaxf(__int_as_float(m), 0.0f);
        atomicMax(&g_slot[0][b][rowch * ROWCH + r], ~__float_as_uint(dr));
    }
    {
        float dc0 = fmaxf(cmin0, 0.0f);
        float dc1 = fmaxf(cmin1, 0.0f);
        atomicMax(&g_slot[1][b][colIdx + 0], ~__float_as_uint(dc0));
        atomicMax(&g_slot[1][b][colIdx + 1], ~__float_as_uint(dc1));
    }
}

// Combine (R13): vectorized decode + weighted reduce; last block finishes.
__global__ __launch_bounds__(256) void combine_kernel(
    const float* __restrict__ w1,
    const float* __restrict__ w2,
    float* __restrict__ out)
{
    __shared__ float s[4][8];
    __shared__ int sLast;

    const int tid = threadIdx.x;
    const int g = blockIdx.x * 256 + tid;             // 0..16383 uint4 groups
    const int dir = g >> 13;

    const uint4 sv = __ldcg((const uint4*)&g_slot[0][0][0] + g);
    const float4 wv = (dir == 0) ? ((const float4*)w1)[g]
                                 : ((const float4*)w2)[g - 8192];
    float n = __uint_as_float(~sv.x) * wv.x;
    n = fmaf(__uint_as_float(~sv.y), wv.y, n);
    n = fmaf(__uint_as_float(~sv.z), wv.z, n);
    n = fmaf(__uint_as_float(~sv.w), wv.w, n);
    float dsum = (wv.x + wv.y) + (wv.z + wv.w);

    float num0 = (dir == 0) ? n : 0.f;
    float den0 = (dir == 0) ? dsum : 0.f;
    float num1 = (dir == 0) ? 0.f : n;
    float den1 = (dir == 0) ? 0.f : dsum;

    #pragma unroll
    for (int off = 16; off > 0; off >>= 1) {
        num0 += __shfl_down_sync(0xffffffffu, num0, off);
        den0 += __shfl_down_sync(0xffffffffu, den0, off);
        num1 += __shfl_down_sync(0xffffffffu, num1, off);
        den1 += __shfl_down_sync(0xffffffffu, den1, off);
    }
    const int wid = tid >> 5;
    if ((tid & 31) == 0) {
        s[0][wid] = num0; s[1][wid] = den0;
        s[2][wid] = num1; s[3][wid] = den1;
    }
    __syncthreads();
    if (tid == 0) {
        float a0 = 0, a1 = 0, a2 = 0, a3 = 0;
        #pragma unroll
        for (int i = 0; i < 8; i++) {
            a0 += s[0][i]; a1 += s[1][i]; a2 += s[2][i]; a3 += s[3][i];
        }
        g_part[blockIdx.x][0] = a0; g_part[blockIdx.x][1] = a1;
        g_part[blockIdx.x][2] = a2; g_part[blockIdx.x][3] = a3;
        __threadfence();
        sLast = (atomicAdd(&g_done, 1) == NCOMB - 1);
    }
    __syncthreads();

    if (sLast) {
        __threadfence();
        volatile float (*gp)[4] = g_part;
        float a0 = 0.f, a1 = 0.f, a2 = 0.f, a3 = 0.f;
        if (tid < 64) {
            a0 = gp[tid][0]; a1 = gp[tid][1]; a2 = gp[tid][2]; a3 = gp[tid][3];
        }
        #pragma unroll
        for (int off = 16; off > 0; off >>= 1) {
            a0 += __shfl_down_sync(0xffffffffu, a0, off);
            a1 += __shfl_down_sync(0xffffffffu, a1, off);
            a2 += __shfl_down_sync(0xffffffffu, a2, off);
            a3 += __shfl_down_sync(0xffffffffu, a3, off);
        }
        __syncthreads();
        if ((tid & 31) == 0 && tid < 64) {
            s[0][wid] = a0; s[1][wid] = a1; s[2][wid] = a2; s[3][wid] = a3;
        }
        __syncthreads();
        if (tid == 0) {
            float N0 = s[0][0] + s[0][1];
            float D0 = s[1][0] + s[1][1];
            float N1 = s[2][0] + s[2][1];
            float D1 = s[3][0] + s[3][1];
            out[0] = 0.5f * (N0 / D0 + N1 / D1);
        }
    }
}

extern "C" void kernel_launch(void* const* d_in, const int* in_sizes, int n_in,
                              void* d_out, int out_size)
{
    const float* xyz1 = (const float*)d_in[0];
    const float* xyz2 = (const float*)d_in[1];
    const float* w1   = (const float*)d_in[2];
    const float* w2   = (const float*)d_in[3];
    float* out        = (float*)d_out;

    min_dist_kernel<<<NBLOCKS, BDIM>>>(xyz1, xyz2);
    combine_kernel<<<NCOMB, 256>>>(w1, w2, out);
}

// round 15
// speedup vs baseline: 1.1235x; 1.1235x over previous
#include <cuda_runtime.h>
#include <cuda_bf16.h>

#define NPTS 8192
#define NB 4
#define BDIM 128
#define ROWCH 512                       // rows per block
#define COLS_PER_BLK 512                // 4 warps x 128 cols
#define NROWCH (NPTS / ROWCH)           // 16
#define NCOLB (NPTS / COLS_PER_BLK)     // 16
#define NBLOCKS (NB * NROWCH * NCOLB)   // 1024
#define NCOMB 64

// Per-(dir,b,a) running min, key = ~bits(d), d>=0 -> min == atomicMax.
// Zero-init; idempotent across graph replays.
__device__ unsigned g_slot[2][NB][NPTS] = {};
__device__ float g_part[NCOMB][4];
__device__ int g_done;

#define PACK2(dst, lo, hi) \
    asm("mov.b64 %0, {%1, %2};" : "=l"(dst) : "r"(__float_as_uint(lo)), "r"(__float_as_uint(hi)))
#define UNPACK2(lo, hi, src) \
    { unsigned _ulo, _uhi; \
      asm("mov.b64 {%0, %1}, %2;" : "=r"(_ulo), "=r"(_uhi) : "l"(src)); \
      lo = __uint_as_float(_ulo); hi = __uint_as_float(_uhi); }
#define ADD2(d, a, b) \
    asm("add.rn.f32x2 %0, %1, %2;" : "=l"(d) : "l"(a), "l"(b))
#define FMA2(d, a, b, c) \
    asm("fma.rn.f32x2 %0, %1, %2, %3;" : "=l"(d) : "l"(a), "l"(b), "l"(c))
#define LDS_V2U64(r0, r1, addr) \
    asm volatile("ld.shared.v2.u64 {%0, %1}, [%2];" : "=l"(r0), "=l"(r1) : "r"(addr))

// Symmetric kernel: block = 512 rows (xyz1) x 512 cols (xyz2). Each distance
// computed ONCE. Col-mins accumulate in each lane's registers (4 cols/lane);
// row-mins via 16-row register batches + shfl halving tree (no REDUX).
__global__ __launch_bounds__(BDIM, 7) void min_dist_kernel(
    const float* __restrict__ xyz1,
    const float* __restrict__ xyz2)
{
    // Row records (x,x,y,y | z,z,s1,s1) dup-packed: 512 * 32B = 16KB
    __shared__ __align__(16) unsigned long long sRow[ROWCH * 4];

    const int bx = blockIdx.x;
    if (bx == 0 && threadIdx.x == 0) g_done = 0;   // for combine (stream-ordered)

    const int colb  = bx & (NCOLB - 1);
    const int rowch = (bx >> 4) & (NROWCH - 1);
    const int b     = bx >> 8;

    const int tid  = threadIdx.x;
    const int wid  = tid >> 5;
    const int lane = tid & 31;
    const int rowBase = rowch * ROWCH;

    // Prologue 1: dup-pack this block's 512 rows of xyz1 into smem.
    {
        const float2* R2 = (const float2*)(xyz1 + (size_t)(b * NPTS + rowBase) * 3);
        #pragma unroll
        for (int i = 0; i < (ROWCH / 2) / BDIM; i++) {   // 2 row-pairs per thread
            const int j = i * BDIM + tid;
            float2 q0 = R2[3 * j + 0];
            float2 q1 = R2[3 * j + 1];
            float2 q2 = R2[3 * j + 2];
            float s0 = q0.x * q0.x + q0.y * q0.y + q1.x * q1.x;
            float s1v = q1.y * q1.y + q2.x * q2.x + q2.y * q2.y;
            float4* dst = (float4*)sRow;
            dst[(2 * j + 0) * 2 + 0] = make_float4(q0.x, q0.x, q0.y, q0.y);
            dst[(2 * j + 0) * 2 + 1] = make_float4(q1.x, q1.x, s0, s0);
            dst[(2 * j + 1) * 2 + 0] = make_float4(q1.y, q1.y, q2.x, q2.x);
            dst[(2 * j + 1) * 2 + 1] = make_float4(q2.y, q2.y, s1v, s1v);
        }
    }

    // Prologue 2: this lane's TWO col-pairs (4 cols) from xyz2 into regs.
    const int c0 = colb * COLS_PER_BLK + wid * 128 + lane * 2;   // pair 0: c0,c0+1
    const int c1 = c0 + 64;                                      // pair 1
    unsigned long long X0, Y0, Z0, W0, X1, Y1, Z1, W1;
    {
        const float2* C2 = (const float2*)(xyz2 + (size_t)(b * NPTS + c0) * 3);
        float2 q0 = C2[0], q1 = C2[1], q2 = C2[2];
        PACK2(X0, -2.0f * q0.x, -2.0f * q1.y);
        PACK2(Y0, -2.0f * q0.y, -2.0f * q2.x);
        PACK2(Z0, -2.0f * q1.x, -2.0f * q2.y);
        PACK2(W0, q0.x * q0.x + q0.y * q0.y + q1.x * q1.x,
                  q1.y * q1.y + q2.x * q2.x + q2.y * q2.y);
    }
    {
        const float2* C2 = (const float2*)(xyz2 + (size_t)(b * NPTS + c1) * 3);
        float2 q0 = C2[0], q1 = C2[1], q2 = C2[2];
        PACK2(X1, -2.0f * q0.x, -2.0f * q1.y);
        PACK2(Y1, -2.0f * q0.y, -2.0f * q2.x);
        PACK2(Z1, -2.0f * q1.x, -2.0f * q2.y);
        PACK2(W1, q0.x * q0.x + q0.y * q0.y + q1.x * q1.x,
                  q1.y * q1.y + q2.x * q2.x + q2.y * q2.y);
    }

    float cmin0 = 3.402823e38f, cmin1 = 3.402823e38f;
    float cmin2 = 3.402823e38f, cmin3 = 3.402823e38f;

    const unsigned sbase = (unsigned)__cvta_generic_to_shared(sRow);
    __syncthreads();

    unsigned* rowSlot = &g_slot[0][b][rowBase];

    for (int rb = 0; rb < ROWCH; rb += 16) {
        float v[16];
        #pragma unroll
        for (int i = 0; i < 16; i++) {
            unsigned long long xx, yy, zz, ss, t0, t1, e0, e1;
            LDS_V2U64(xx, yy, sbase + (rb + i) * 32);
            LDS_V2U64(zz, ss, sbase + (rb + i) * 32 + 16);
            FMA2(t0, X0, xx, W0);
            FMA2(t0, Y0, yy, t0);
            FMA2(t0, Z0, zz, t0);
            FMA2(t1, X1, xx, W1);
            FMA2(t1, Y1, yy, t1);
            FMA2(t1, Z1, zz, t1);
            ADD2(e0, t0, ss);                // true distances (s1 included)
            ADD2(e1, t1, ss);
            float a0, a1, b0, b1;
            UNPACK2(a0, a1, e0);
            UNPACK2(b0, b1, e1);
            cmin0 = fminf(cmin0, a0);
            cmin1 = fminf(cmin1, a1);
            cmin2 = fminf(cmin2, b0);
            cmin3 = fminf(cmin3, b1);
            v[i] = fminf(fminf(a0, a1), fminf(b0, b1));
        }

        // Cross-lane row-min: pure exchange (off=16), then halving tree.
        #pragma unroll
        for (int i = 0; i < 16; i++)
            v[i] = fminf(v[i], __shfl_xor_sync(0xffffffffu, v[i], 16));
        #pragma unroll
        for (int off = 8; off >= 1; off >>= 1) {
            #pragma unroll
            for (int i = 0; i < off; i++) {
                float send = (lane & off) ? v[i] : v[i + off];
                float recv = __shfl_xor_sync(0xffffffffu, send, off);
                float keep = (lane & off) ? v[i + off] : v[i];
                v[i] = fminf(keep, recv);
            }
        }
        // lane (0..15) holds full row-min of row rb + lane.
        if (lane < 16) {
            float dr = fmaxf(v[0], 0.0f);
            atomicMax(&rowSlot[rb + lane], ~__float_as_uint(dr));
        }
    }

    // Tail: publish 4 col-mins per lane.
    atomicMax(&g_slot[1][b][c0 + 0], ~__float_as_uint(fmaxf(cmin0, 0.0f)));
    atomicMax(&g_slot[1][b][c0 + 1], ~__float_as_uint(fmaxf(cmin1, 0.0f)));
    atomicMax(&g_slot[1][b][c1 + 0], ~__float_as_uint(fmaxf(cmin2, 0.0f)));
    atomicMax(&g_slot[1][b][c1 + 1], ~__float_as_uint(fmaxf(cmin3, 0.0f)));
}

// Combine (R13): vectorized decode + weighted reduce; last block finishes.
__global__ __launch_bounds__(256) void combine_kernel(
    const float* __restrict__ w1,
    const float* __restrict__ w2,
    float* __restrict__ out)
{
    __shared__ float s[4][8];
    __shared__ int sLast;

    const int tid = threadIdx.x;
    const int g = blockIdx.x * 256 + tid;             // 0..16383 uint4 groups
    const int dir = g >> 13;

    const uint4 sv = __ldcg((const uint4*)&g_slot[0][0][0] + g);
    const float4 wv = (dir == 0) ? ((const float4*)w1)[g]
                                 : ((const float4*)w2)[g - 8192];
    float n = __uint_as_float(~sv.x) * wv.x;
    n = fmaf(__uint_as_float(~sv.y), wv.y, n);
    n = fmaf(__uint_as_float(~sv.z), wv.z, n);
    n = fmaf(__uint_as_float(~sv.w), wv.w, n);
    float dsum = (wv.x + wv.y) + (wv.z + wv.w);

    float num0 = (dir == 0) ? n : 0.f;
    float den0 = (dir == 0) ? dsum : 0.f;
    float num1 = (dir == 0) ? 0.f : n;
    float den1 = (dir == 0) ? 0.f : dsum;

    #pragma unroll
    for (int off = 16; off > 0; off >>= 1) {
        num0 += __shfl_down_sync(0xffffffffu, num0, off);
        den0 += __shfl_down_sync(0xffffffffu, den0, off);
        num1 += __shfl_down_sync(0xffffffffu, num1, off);
        den1 += __shfl_down_sync(0xffffffffu, den1, off);
    }
    const int wid = tid >> 5;
    if ((tid & 31) == 0) {
        s[0][wid] = num0; s[1][wid] = den0;
        s[2][wid] = num1; s[3][wid] = den1;
    }
    __syncthreads();
    if (tid == 0) {
        float a0 = 0, a1 = 0, a2 = 0, a3 = 0;
        #pragma unroll
        for (int i = 0; i < 8; i++) {
            a0 += s[0][i]; a1 += s[1][i]; a2 += s[2][i]; a3 += s[3][i];
        }
        g_part[blockIdx.x][0] = a0; g_part[blockIdx.x][1] = a1;
        g_part[blockIdx.x][2] = a2; g_part[blockIdx.x][3] = a3;
        __threadfence();
        sLast = (atomicAdd(&g_done, 1) == NCOMB - 1);
    }
    __syncthreads();

    if (sLast) {
        __threadfence();
        volatile float (*gp)[4] = g_part;
        float a0 = 0.f, a1 = 0.f, a2 = 0.f, a3 = 0.f;
        if (tid < 64) {
            a0 = gp[tid][0]; a1 = gp[tid][1]; a2 = gp[tid][2]; a3 = gp[tid][3];
        }
        #pragma unroll
        for (int off = 16; off > 0; off >>= 1) {
            a0 += __shfl_down_sync(0xffffffffu, a0, off);
            a1 += __shfl_down_sync(0xffffffffu, a1, off);
            a2 += __shfl_down_sync(0xffffffffu, a2, off);
            a3 += __shfl_down_sync(0xffffffffu, a3, off);
        }
        __syncthreads();
        if ((tid & 31) == 0 && tid < 64) {
            s[0][wid] = a0; s[1][wid] = a1; s[2][wid] = a2; s[3][wid] = a3;
        }
        __syncthreads();
        if (tid == 0) {
            float N0 = s[0][0] + s[0][1];
            float D0 = s[1][0] + s[1][1];
            float N1 = s[2][0] + s[2][1];
            float D1 = s[3][0] + s[3][1];
            out[0] = 0.5f * (N0 / D0 + N1 / D1);
        }
    }
}

extern "C" void kernel_launch(void* const* d_in, const int* in_sizes, int n_in,
                              void* d_out, int out_size)
{
    const float* xyz1 = (const float*)d_in[0];
    const float* xyz2 = (const float*)d_in[1];
    const float* w1   = (const float*)d_in[2];
    const float* w2   = (const float*)d_in[3];
    float* out        = (float*)d_out;

    min_dist_kernel<<<NBLOCKS, BDIM>>>(xyz1, xyz2);
    combine_kernel<<<NCOMB, 256>>>(w1, w2, out);
}